// round 6
// baseline (speedup 1.0000x reference)
#include <cuda_runtime.h>

#define HH 1024
#define WW 1024
#define RC 19                  // cone radius = n_steps-1
#define REG 39                 // 2*RC+1
#define CELLS (REG*REG)        // 1521
#define PITCH 48               // smem row width (floats)
#define SROWS 41               // REG + 2 halo rows
#define NSIM 416               // 13 warps; warp w owns rows 3w..3w+2
#define FILLB 512
#define COEFB ((8*CELLS + 255)/256)   // 48

#define PDL_TRIGGER() asm volatile("griddepcontrol.launch_dependents;")
#define PDL_WAIT()    asm volatile("griddepcontrol.wait;" ::: "memory")
#define BAR1_128()    asm volatile("bar.sync 1, 128;" ::: "memory")

// Cell-major coefficients: g_coefT[cell*8 + k]; gain separate.
__device__ float g_coefT[CELLS * 8];
__device__ float g_gain[CELLS];

__constant__ int   c_di[8]   = {-1, -1, -1,  0,  0,  1,  1,  1};
__constant__ int   c_dj[8]   = {-1,  0,  1, -1,  1, -1,  0,  1};
__constant__ float c_dist[8] = {0.83f, 1.0f, 0.83f, 1.0f, 1.0f, 0.83f, 1.0f, 0.83f};
__constant__ float c_ui[8]   = {-0.70710678f, -1.0f, -0.70710678f, 0.0f, 0.0f,
                                 0.70710678f,  1.0f,  0.70710678f};
__constant__ float c_uj[8]   = {-0.70710678f,  0.0f,  0.70710678f, -1.0f, 1.0f,
                                -0.70710678f,  0.0f,  0.70710678f};

// ---------------------------------------------------------------------------
// K1 (fused): blocks [0,FILLB) fill the output with n_steps (sim overwrites
// the cone region strictly later, ordered by PDL); rest compute coefs + gain.
// ---------------------------------------------------------------------------
__global__ void __launch_bounds__(256)
prep_kernel(const float* __restrict__ height,
            const float* __restrict__ age,
            const float* __restrict__ moisture,
            const float* __restrict__ la, const float* __restrict__ lb,
            const float* __restrict__ lg, const float* __restrict__ ld,
            const float* __restrict__ ws, const float* __restrict__ wd,
            const int*   __restrict__ ip,
            const int*   __restrict__ nsp,
            float4*      __restrict__ out4) {
    if (blockIdx.x < FILLB) {
        float v = (float)(*nsp);
        int i = blockIdx.x * 256 + threadIdx.x;
        float4 f = make_float4(v, v, v, v);
        out4[i] = f;
        out4[i + FILLB * 256] = f;
        PDL_TRIGGER();
        return;
    }

    int idx = (blockIdx.x - FILLB) * 256 + threadIdx.x;
    if (idx < 8 * CELLS) {
        int k    = idx / CELLS;
        int cell = idx - k * CELLS;
        int r = cell / REG;
        int c = cell - r * REG;
        int gi = ip[0] - RC + r;
        int gj = ip[1] - RC + c;
        bool ingrid = (gi >= 0) && (gi < HH) && (gj >= 0) && (gj < WW);

        if (k == 0) {
            float g = 0.0f;
            if (ingrid) {
                float alpha = expf(la[0]);
                float beta  = expf(lb[0]);
                float a = age[gi * WW + gj];
                float m = moisture[gi * WW + gj];
                float ratio = fmaxf(a / 30.0f, 1e-6f);            // T_MAX = 30
                float below = exp2f(powf(ratio, alpha)) - 1.0f;   // (1+P)^(r^a)-1
                float af = (a < 30.0f) ? below : 1.0f;
                g = af * expf(-beta * m);
            }
            g_gain[cell] = g;
        }

        float coef = 0.0f;
        if (ingrid) {
            int ni = gi + c_di[k];
            int nj = gj + c_dj[k];
            if (ni >= 0 && ni < HH && nj >= 0 && nj < WW) {   // valid-mask
                float gamma = expf(lg[0]);
                float delta = expf(ld[0]);
                float dh = height[gi * WW + gj] - height[ni * WW + nj];
                float phi = (dh <= 0.0f) ? expf(gamma * dh)
                                         : (1.0f + gamma * sqrtf(dh));
                float s  = ws[ni * WW + nj];
                float dr = wd[ni * WW + nj];
                float wy = s * cosf(dr);
                float wx = s * sinf(dr);
                float align = c_ui[k] * wy + c_uj[k] * wx;
                float wf = fminf(fmaxf(expf(delta * align), -2.0f), 2.0f);
                coef = c_dist[k] * wf * phi;
            }
        }
        g_coefT[cell * 8 + k] = coef;
    }
    PDL_TRIGGER();
}

// ---------------------------------------------------------------------------
// K2: phased light-cone sim.
//   Phase A (t=1..5):  11x11, warp 0, smem state, __syncwarp.
//   Phase B (t=6..12): 25x25, warps 0-3, smem state, bar.sync 1,128.
//   Phase C (t=13..18+?): full 13-warp shuffle loop, branchless.
// Arrival via telescoped sum: arr = N - sum_{t=1}^{N-1} s_t  (prev0 = 0).
// ---------------------------------------------------------------------------
__global__ void __launch_bounds__(NSIM, 1)
sim_kernel(const float* __restrict__ ignv,
           const int*   __restrict__ ip,
           const int*   __restrict__ nsp,
           const int*   __restrict__ nssp,
           float*       __restrict__ out) {
    __shared__ float sbuf[2][SROWS * PITCH];
    __shared__ float accb[SROWS * PITCH];

    int tid = threadIdx.x;
    for (int i = tid; i < (2 * SROWS * PITCH) / 4; i += NSIM)
        ((float4*)sbuf)[i] = make_float4(0.f, 0.f, 0.f, 0.f);
    for (int i = tid; i < (SROWS * PITCH) / 4; i += NSIM)
        ((float4*)accb)[i] = make_float4(0.f, 0.f, 0.f, 0.f);

    // Input scalars are launch-stable: safe to read pre-wait.
    int ns  = nsp[0];
    int nss = nssp[0];
    float ig  = ignv[0];
    float fns = (float)ns;
    int or0 = ip[0] - RC;
    int oc0 = ip[1] - RC;
    bool fast = (ns == 20) && (nss == 1);

    int w    = tid >> 5;
    int lane = tid & 31;
    int lrow = lane / 10;              // 0,1,2 workers; 3 = idle (lanes 30,31)
    int g    = lane - lrow * 10;
    bool worker = (lrow < 3);
    int row = worker ? (w * 3 + lrow) : 0;   // 0..38
    int c0  = g * 4;
    // branchless smem source row: lrow0 -> row above (smem 'row'),
    // lrow2 -> row below (smem row+2), others -> dummy zero row 40.
    int srow = (lrow == 0) ? row : ((lrow == 2) ? (row + 2) : 40);
    bool isU = (lrow == 0), isD = (lrow == 2);

    int a = 3 * w;
    int wmin = (RC >= a && RC <= a + 2) ? 0 : ((a > RC) ? (a - RC) : (RC - (a + 2)));

    PDL_WAIT();   // prep (fill + coefs) complete & visible past this point

    __syncthreads();                 // smem zeros visible
    if (tid == 0)
        sbuf[0][(RC + 1) * PITCH + (RC + 4)] = ig;   // ignition (state_0)

    int tstart = 1;
    if (fast) {
        // ---------------- Phase A: t=1..5, warp 0, 11x11 ----------------
        if (tid < 32) {
            float cfA[4][8], gnA[4], curA[4], accA[4];
            int pA[4]; bool vA[4];
            #pragma unroll
            for (int q = 0; q < 4; q++) {
                int m = tid + 32 * q;
                vA[q] = (m < 121);
                int mm = vA[q] ? m : 0;
                int r = mm / 11, c = mm - (mm / 11) * 11;
                int rr = RC - 5 + r, cc = RC - 5 + c;
                pA[q] = (rr + 1) * PITCH + cc + 4;
                curA[q] = 0.f; accA[q] = 0.f; gnA[q] = 0.f;
                #pragma unroll
                for (int k = 0; k < 8; k++) cfA[q][k] = 0.f;
                if (vA[q]) {
                    int cell = rr * REG + cc;
                    float4 qa = *(const float4*)(g_coefT + cell * 8);
                    float4 qb = *(const float4*)(g_coefT + cell * 8 + 4);
                    cfA[q][0] = qa.x; cfA[q][1] = qa.y; cfA[q][2] = qa.z; cfA[q][3] = qa.w;
                    cfA[q][4] = qb.x; cfA[q][5] = qb.y; cfA[q][6] = qb.z; cfA[q][7] = qb.w;
                    gnA[q] = g_gain[cell];
                    if (rr == RC && cc == RC) curA[q] = ig;
                }
            }
            int cba = 0;
            for (int t = 1; t <= 5; t++) {
                __syncwarp();
                const float* rb = sbuf[cba];
                float*       wb = sbuf[cba ^ 1];
                #pragma unroll
                for (int q = 0; q < 4; q++) {
                    if (vA[q]) {
                        const float* p0 = rb + pA[q] - PITCH;
                        const float* p1 = rb + pA[q];
                        const float* p2 = rb + pA[q] + PITCH;
                        float ta = cfA[q][0] * p0[-1] + cfA[q][1] * p0[0];
                        ta = fmaf(cfA[q][2], p0[1], ta);
                        ta = fmaf(cfA[q][3], p1[-1], ta);
                        float tb = cfA[q][4] * p1[1] + cfA[q][5] * p2[-1];
                        tb = fmaf(cfA[q][6], p2[0], tb);
                        tb = fmaf(cfA[q][7], p2[1], tb);
                        curA[q] = fminf(fmaf(gnA[q], ta + tb, curA[q]), 1.0f);
                        wb[pA[q]] = curA[q];
                        accA[q] += curA[q];
                    }
                }
                cba ^= 1;
            }
            __syncwarp();
            #pragma unroll
            for (int q = 0; q < 4; q++)
                if (vA[q]) accb[pA[q]] = accA[q];
        }
        // ---------------- Phase B: t=6..12, warps 0-3, 25x25 ----------------
        if (tid < 128) {
            float cfB[5][8], gnB[5], curB[5], accB[5];
            int pB[5]; bool vB[5];
            #pragma unroll
            for (int q = 0; q < 5; q++) {
                int m = tid + 128 * q;
                vB[q] = (m < 625);
                int mm = vB[q] ? m : 0;
                int r = mm / 25, c = mm - (mm / 25) * 25;
                int rr = RC - 12 + r, cc = RC - 12 + c;
                pB[q] = (rr + 1) * PITCH + cc + 4;
                accB[q] = 0.f; gnB[q] = 0.f;
                #pragma unroll
                for (int k = 0; k < 8; k++) cfB[q][k] = 0.f;
                if (vB[q]) {
                    int cell = rr * REG + cc;
                    float4 qa = *(const float4*)(g_coefT + cell * 8);
                    float4 qb = *(const float4*)(g_coefT + cell * 8 + 4);
                    cfB[q][0] = qa.x; cfB[q][1] = qa.y; cfB[q][2] = qa.z; cfB[q][3] = qa.w;
                    cfB[q][4] = qb.x; cfB[q][5] = qb.y; cfB[q][6] = qb.z; cfB[q][7] = qb.w;
                    gnB[q] = g_gain[cell];
                }
            }
            BAR1_128();                       // phase A writes visible
            #pragma unroll
            for (int q = 0; q < 5; q++)       // state_5 lives in sbuf[1]
                curB[q] = vB[q] ? sbuf[1][pB[q]] : 0.f;
            for (int t = 6; t <= 12; t++) {
                const float* rb = sbuf[(t - 1) & 1];
                float*       wb = sbuf[t & 1];
                #pragma unroll
                for (int q = 0; q < 5; q++) {
                    if (vB[q]) {
                        const float* p0 = rb + pB[q] - PITCH;
                        const float* p1 = rb + pB[q];
                        const float* p2 = rb + pB[q] + PITCH;
                        float ta = cfB[q][0] * p0[-1] + cfB[q][1] * p0[0];
                        ta = fmaf(cfB[q][2], p0[1], ta);
                        ta = fmaf(cfB[q][3], p1[-1], ta);
                        float tb = cfB[q][4] * p1[1] + cfB[q][5] * p2[-1];
                        tb = fmaf(cfB[q][6], p2[0], tb);
                        tb = fmaf(cfB[q][7], p2[1], tb);
                        curB[q] = fminf(fmaf(gnB[q], ta + tb, curB[q]), 1.0f);
                        wb[pB[q]] = curB[q];
                        accB[q] += curB[q];
                    }
                }
                BAR1_128();
            }
            #pragma unroll
            for (int q = 0; q < 5; q++)
                if (vB[q]) accb[pB[q]] += accB[q];
        }
        __syncthreads();   // handoff: state_12 in sbuf[0], acc(1..12) in accb
        tstart = 13;
    }

    // Phase C coefficients (loaded AFTER phases to keep reg liveness disjoint)
    float cf[8][4], gn[4], cur[4], acc[4];
    #pragma unroll
    for (int i = 0; i < 4; i++) {
        gn[i] = 0.f; cur[i] = 0.f; acc[i] = 0.f;
        #pragma unroll
        for (int k = 0; k < 8; k++) cf[k][i] = 0.f;
        if (worker && (c0 + i < REG)) {
            int cell = row * REG + c0 + i;
            float4 qa = *(const float4*)(g_coefT + cell * 8);
            float4 qb = *(const float4*)(g_coefT + cell * 8 + 4);
            cf[0][i] = qa.x; cf[1][i] = qa.y; cf[2][i] = qa.z; cf[3][i] = qa.w;
            cf[4][i] = qb.x; cf[5][i] = qb.y; cf[6][i] = qb.z; cf[7][i] = qb.w;
            gn[i] = g_gain[cell];
        }
    }
    if (fast) {
        if (worker) {
            const float* sp = sbuf[0] + (row + 1) * PITCH + c0 + 4;
            float4 cv = *(const float4*)sp;
            cur[0] = cv.x; cur[1] = cv.y; cur[2] = cv.z; cur[3] = cv.w;
            const float* ap = accb + (row + 1) * PITCH + c0 + 4;
            float4 av = *(const float4*)ap;
            acc[0] = av.x; acc[1] = av.y; acc[2] = av.z; acc[3] = av.w;
        }
    } else {
        // ignition in register (cell (RC,RC) = warp 6, lane 14, slot 3)
        if (w == 6 && lane == 14) cur[3] = ig;
        __syncthreads();   // order ignition STS / keep phases' barrier parity
    }

    const unsigned FULL = 0xffffffffu;
    int cb = (tstart - 1) & 1;    // buffer holding state_{tstart-1}

    for (int t = tstart; t < ns; t++) {          // step t=ns has weight 0
        bool wact = (t * nss >= wmin);           // warp-uniform gate
        for (int s = 0; s < nss; s++) {
            if (wact) {
                float oL = __shfl_sync(FULL, cur[3], lane - 1);
                float oR = __shfl_sync(FULL, cur[0], lane + 1);
                float u0 = __shfl_sync(FULL, cur[0], lane - 10);
                float u1 = __shfl_sync(FULL, cur[1], lane - 10);
                float u2 = __shfl_sync(FULL, cur[2], lane - 10);
                float u3 = __shfl_sync(FULL, cur[3], lane - 10);
                float uL = __shfl_sync(FULL, cur[3], lane - 11);
                float uR = __shfl_sync(FULL, cur[0], lane - 9);
                float d0 = __shfl_sync(FULL, cur[0], lane + 10);
                float d1 = __shfl_sync(FULL, cur[1], lane + 10);
                float d2 = __shfl_sync(FULL, cur[2], lane + 10);
                float d3 = __shfl_sync(FULL, cur[3], lane + 10);
                float dL = __shfl_sync(FULL, cur[3], lane + 9);
                float dR = __shfl_sync(FULL, cur[0], lane + 11);
                // branchless warp-boundary row fetch (dummy zero row for lrow1/idle)
                const float* rp = sbuf[cb] + srow * PITCH;
                float  e0 = rp[c0 + 3];
                float4 qv = *(const float4*)(rp + c0 + 4);
                float  e1 = rp[c0 + 8];
                uL = isU ? e0   : uL;  u0 = isU ? qv.x : u0;
                u1 = isU ? qv.y : u1;  u2 = isU ? qv.z : u2;
                u3 = isU ? qv.w : u3;  uR = isU ? e1   : uR;
                dL = isD ? e0   : dL;  d0 = isD ? qv.x : d0;
                d1 = isD ? qv.y : d1;  d2 = isD ? qv.z : d2;
                d3 = isD ? qv.w : d3;  dR = isD ? e1   : dR;
                if (g == 0) { uL = 0.f; oL = 0.f; dL = 0.f; }

                float up[6] = {uL, u0, u1, u2, u3, uR};
                float mi[6] = {oL, cur[0], cur[1], cur[2], cur[3], oR};
                float dn[6] = {dL, d0, d1, d2, d3, dR};
                #pragma unroll
                for (int i = 0; i < 4; i++) {
                    float ta = cf[0][i] * up[i] + cf[1][i] * up[i + 1];
                    ta = fmaf(cf[2][i], up[i + 2], ta);
                    ta = fmaf(cf[3][i], mi[i], ta);
                    float tb = cf[4][i] * mi[i + 2] + cf[5][i] * dn[i];
                    tb = fmaf(cf[6][i], dn[i + 1], tb);
                    tb = fmaf(cf[7][i], dn[i + 2], tb);
                    cur[i] = fminf(fmaf(gn[i], ta + tb, cur[i]), 1.0f);
                }
                if (worker && lrow != 1)         // publish boundary rows only
                    *(float4*)(sbuf[cb ^ 1] + (row + 1) * PITCH + c0 + 4) =
                        make_float4(cur[0], cur[1], cur[2], cur[3]);
            }
            __syncthreads();
            cb ^= 1;
        }
        if (wact) {
            #pragma unroll
            for (int i = 0; i < 4; i++) acc[i] += cur[i];
        }
    }

    if (worker) {
        int gi = or0 + row;
        if (gi >= 0 && gi < HH) {
            #pragma unroll
            for (int i = 0; i < 4; i++) {
                int gj = oc0 + c0 + i;
                if ((c0 + i < REG) && gj >= 0 && gj < WW)
                    out[gi * WW + gj] = fns - acc[i];
            }
        }
    }
}

// ---------------------------------------------------------------------------
extern "C" void kernel_launch(void* const* d_in, const int* in_sizes, int n_in,
                              void* d_out, int out_size) {
    const float* height   = (const float*)d_in[0];
    const float* age      = (const float*)d_in[1];
    const float* moisture = (const float*)d_in[2];
    const float* la       = (const float*)d_in[3];
    const float* lb       = (const float*)d_in[4];
    const float* lg       = (const float*)d_in[5];
    const float* ld       = (const float*)d_in[6];
    const float* ws       = (const float*)d_in[7];
    const float* wd       = (const float*)d_in[8];
    const float* ignv     = (const float*)d_in[9];
    const int*   ip       = (const int*)d_in[10];
    const int*   ns       = (const int*)d_in[11];
    const int*   nss      = (const int*)d_in[12];
    float* out = (float*)d_out;

    prep_kernel<<<FILLB + COEFB, 256>>>(height, age, moisture,
                                        la, lb, lg, ld, ws, wd, ip, ns,
                                        (float4*)out);

    cudaLaunchConfig_t cfg = {};
    cfg.gridDim  = dim3(1, 1, 1);
    cfg.blockDim = dim3(NSIM, 1, 1);
    cudaLaunchAttribute attr[1];
    attr[0].id = cudaLaunchAttributeProgrammaticStreamSerialization;
    attr[0].val.programmaticStreamSerializationAllowed = 1;
    cfg.attrs = attr;
    cfg.numAttrs = 1;
    cudaLaunchKernelEx(&cfg, sim_kernel, ignv, ip, ns, nss, out);
}

// round 7
// speedup vs baseline: 1.1358x; 1.1358x over previous
#include <cuda_runtime.h>

#define HH 1024
#define WW 1024
#define RC 19                  // cone radius = n_steps-1
#define REG 39                 // 2*RC+1
#define CELLS (REG*REG)        // 1521
#define PITCH 48               // smem row width (floats)
#define SROWS 41               // REG + 2 halo rows (row 40 = always-zero dummy)
#define NSIM 416               // 13 warps; warp w owns rows 3w..3w+2
#define FILLB 512
#define COEFB ((8*CELLS + 255)/256)   // 48

#define PDL_TRIGGER() asm volatile("griddepcontrol.launch_dependents;")
#define PDL_WAIT()    asm volatile("griddepcontrol.wait;" ::: "memory")

// Cell-major coefficients: g_coefT[cell*8 + k]; gain separate.
__device__ float g_coefT[CELLS * 8];
__device__ float g_gain[CELLS];

__constant__ int   c_di[8]   = {-1, -1, -1,  0,  0,  1,  1,  1};
__constant__ int   c_dj[8]   = {-1,  0,  1, -1,  1, -1,  0,  1};
__constant__ float c_dist[8] = {0.83f, 1.0f, 0.83f, 1.0f, 1.0f, 0.83f, 1.0f, 0.83f};
__constant__ float c_ui[8]   = {-0.70710678f, -1.0f, -0.70710678f, 0.0f, 0.0f,
                                 0.70710678f,  1.0f,  0.70710678f};
__constant__ float c_uj[8]   = {-0.70710678f,  0.0f,  0.70710678f, -1.0f, 1.0f,
                                -0.70710678f,  0.0f,  0.70710678f};

// ---------------------------------------------------------------------------
// K1: coefficients + gain for the 39x39 region ONLY (no fill -> sim's PDL
// wait covers ~1us of work instead of the 4MB fill).
// ---------------------------------------------------------------------------
__global__ void __launch_bounds__(256)
coef_kernel(const float* __restrict__ height,
            const float* __restrict__ age,
            const float* __restrict__ moisture,
            const float* __restrict__ la, const float* __restrict__ lb,
            const float* __restrict__ lg, const float* __restrict__ ld,
            const float* __restrict__ ws, const float* __restrict__ wd,
            const int*   __restrict__ ip) {
    int idx = blockIdx.x * 256 + threadIdx.x;
    if (idx < 8 * CELLS) {
        int k    = idx / CELLS;
        int cell = idx - k * CELLS;
        int r = cell / REG;
        int c = cell - r * REG;
        int gi = ip[0] - RC + r;
        int gj = ip[1] - RC + c;
        bool ingrid = (gi >= 0) && (gi < HH) && (gj >= 0) && (gj < WW);

        if (k == 0) {
            float g = 0.0f;
            if (ingrid) {
                float alpha = expf(la[0]);
                float beta  = expf(lb[0]);
                float a = age[gi * WW + gj];
                float m = moisture[gi * WW + gj];
                float ratio = fmaxf(a / 30.0f, 1e-6f);            // T_MAX = 30
                float below = exp2f(powf(ratio, alpha)) - 1.0f;   // (1+P)^(r^a)-1
                float af = (a < 30.0f) ? below : 1.0f;
                g = af * expf(-beta * m);
            }
            g_gain[cell] = g;
        }

        float coef = 0.0f;
        if (ingrid) {
            int ni = gi + c_di[k];
            int nj = gj + c_dj[k];
            if (ni >= 0 && ni < HH && nj >= 0 && nj < WW) {   // valid-mask
                float gamma = expf(lg[0]);
                float delta = expf(ld[0]);
                float dh = height[gi * WW + gj] - height[ni * WW + nj];
                float phi = (dh <= 0.0f) ? expf(gamma * dh)
                                         : (1.0f + gamma * sqrtf(dh));
                float s  = ws[ni * WW + nj];
                float dr = wd[ni * WW + nj];
                float wy = s * cosf(dr);
                float wx = s * sinf(dr);
                float align = c_ui[k] * wy + c_uj[k] * wx;
                float wf = fminf(fmaxf(expf(delta * align), -2.0f), 2.0f);
                coef = c_dist[k] * wf * phi;
            }
        }
        g_coefT[cell * 8 + k] = coef;
    }
    PDL_TRIGGER();   // after stores: sim's wait sees all coefs
}

// ---------------------------------------------------------------------------
// K2: shuffle-exchange light-cone sim (13 warps, 3 rows/warp, 4 cells/lane).
// Triggers dependents at ENTRY so the fill kernel runs concurrently on other
// SMs. Arrival telescoped: arr = N - sum_{t=1}^{N-1} s_t.
// ---------------------------------------------------------------------------
__global__ void __launch_bounds__(NSIM, 1)
sim_kernel(const float* __restrict__ ignv,
           const int*   __restrict__ ip,
           const int*   __restrict__ nsp,
           const int*   __restrict__ nssp,
           float*       __restrict__ out) {
    PDL_TRIGGER();   // release the concurrent fill immediately

    __shared__ float sbuf[2][SROWS * PITCH];

    int tid = threadIdx.x;
    for (int i = tid; i < (2 * SROWS * PITCH) / 4; i += NSIM)
        ((float4*)sbuf)[i] = make_float4(0.f, 0.f, 0.f, 0.f);

    // Input scalars are launch-stable: safe to read pre-wait.
    int ns  = nsp[0];
    int nss = nssp[0];
    float ig  = ignv[0];
    float fns = (float)ns;
    int or0 = ip[0] - RC;
    int oc0 = ip[1] - RC;

    int w    = tid >> 5;
    int lane = tid & 31;
    int lrow = lane / 10;              // 0,1,2 workers; 3 = idle (lanes 30,31)
    int g    = lane - lrow * 10;
    bool worker = (lrow < 3);
    int row = worker ? (w * 3 + lrow) : 0;   // 0..38
    int c0  = g * 4;
    // branchless boundary-row source: lrow0 -> smem row 'row' (interior row-1),
    // lrow2 -> smem row row+2 (interior row+1), others -> dummy zero row 40.
    int srow = (lrow == 0) ? row : ((lrow == 2) ? (row + 2) : 40);
    bool isU = (lrow == 0), isD = (lrow == 2);

    int a = 3 * w;
    int wmin = (RC >= a && RC <= a + 2) ? 0 : ((a > RC) ? (a - RC) : (RC - (a + 2)));

    PDL_WAIT();   // coefs complete & visible past this point

    float cf[8][4], gn[4], cur[4], acc[4];
    #pragma unroll
    for (int i = 0; i < 4; i++) {
        gn[i] = 0.f; cur[i] = 0.f; acc[i] = 0.f;
        #pragma unroll
        for (int k = 0; k < 8; k++) cf[k][i] = 0.f;
        if (worker && (c0 + i < REG)) {
            int cell = row * REG + c0 + i;
            float4 qa = *(const float4*)(g_coefT + cell * 8);
            float4 qb = *(const float4*)(g_coefT + cell * 8 + 4);
            cf[0][i] = qa.x; cf[1][i] = qa.y; cf[2][i] = qa.z; cf[3][i] = qa.w;
            cf[4][i] = qb.x; cf[5][i] = qb.y; cf[6][i] = qb.z; cf[7][i] = qb.w;
            gn[i] = g_gain[cell];
        }
    }
    // ignition cell (RC,RC): warp 6, lane 14, slot 3. Its row-neighbors (18,20)
    // are warp-6-internal and column neighbors come via shuffle, so no smem
    // ignition store is needed.
    if (w == 6 && lane == 14) cur[3] = ig;

    __syncthreads();   // smem zeros visible before first step

    const unsigned FULL = 0xffffffffu;
    int cb = 0;

    for (int t = 1; t < ns; t++) {              // step t=ns has arrival weight 0
        bool wact = (t * nss >= wmin);          // warp-uniform light-cone gate
        for (int s = 0; s < nss; s++) {
            if (wact) {
                // boundary-row LDS first: 29-cyc latency hides under shuffles
                const float* rp = sbuf[cb] + srow * PITCH;
                float  e0 = rp[c0 + 3];
                float4 qv = *(const float4*)(rp + c0 + 4);
                float  e1 = rp[c0 + 8];

                float oL = __shfl_sync(FULL, cur[3], lane - 1);
                float oR = __shfl_sync(FULL, cur[0], lane + 1);
                float u0 = __shfl_sync(FULL, cur[0], lane - 10);
                float u1 = __shfl_sync(FULL, cur[1], lane - 10);
                float u2 = __shfl_sync(FULL, cur[2], lane - 10);
                float u3 = __shfl_sync(FULL, cur[3], lane - 10);
                float uL = __shfl_sync(FULL, cur[3], lane - 11);
                float uR = __shfl_sync(FULL, cur[0], lane - 9);
                float d0 = __shfl_sync(FULL, cur[0], lane + 10);
                float d1 = __shfl_sync(FULL, cur[1], lane + 10);
                float d2 = __shfl_sync(FULL, cur[2], lane + 10);
                float d3 = __shfl_sync(FULL, cur[3], lane + 10);
                float dL = __shfl_sync(FULL, cur[3], lane + 9);
                float dR = __shfl_sync(FULL, cur[0], lane + 11);

                uL = isU ? e0   : uL;  u0 = isU ? qv.x : u0;
                u1 = isU ? qv.y : u1;  u2 = isU ? qv.z : u2;
                u3 = isU ? qv.w : u3;  uR = isU ? e1   : uR;
                dL = isD ? e0   : dL;  d0 = isD ? qv.x : d0;
                d1 = isD ? qv.y : d1;  d2 = isD ? qv.z : d2;
                d3 = isD ? qv.w : d3;  dR = isD ? e1   : dR;
                if (g == 0) { uL = 0.f; oL = 0.f; dL = 0.f; }

                float up[6] = {uL, u0, u1, u2, u3, uR};
                float mi[6] = {oL, cur[0], cur[1], cur[2], cur[3], oR};
                float dn[6] = {dL, d0, d1, d2, d3, dR};
                #pragma unroll
                for (int i = 0; i < 4; i++) {
                    float ta = cf[0][i] * up[i] + cf[1][i] * up[i + 1];
                    ta = fmaf(cf[2][i], up[i + 2], ta);
                    ta = fmaf(cf[3][i], mi[i], ta);
                    float tb = cf[4][i] * mi[i + 2] + cf[5][i] * dn[i];
                    tb = fmaf(cf[6][i], dn[i + 1], tb);
                    tb = fmaf(cf[7][i], dn[i + 2], tb);
                    // state >= 0 always, so clip(x,0,1) == min(x,1)
                    cur[i] = fminf(fmaf(gn[i], ta + tb, cur[i]), 1.0f);
                }
                if (worker && lrow != 1)         // publish boundary rows only
                    *(float4*)(sbuf[cb ^ 1] + (row + 1) * PITCH + c0 + 4) =
                        make_float4(cur[0], cur[1], cur[2], cur[3]);
            }
            __syncthreads();
            cb ^= 1;
        }
        if (wact) {                              // telescoped arrival accumulator
            #pragma unroll
            for (int i = 0; i < 4; i++) acc[i] += cur[i];
        }
    }

    if (worker) {
        int gi = or0 + row;
        if (gi >= 0 && gi < HH) {
            #pragma unroll
            for (int i = 0; i < 4; i++) {
                int gj = oc0 + c0 + i;
                if ((c0 + i < REG) && gj >= 0 && gj < WW)
                    out[gi * WW + gj] = fns - acc[i];
            }
        }
    }
}

// ---------------------------------------------------------------------------
// K3: fill arrival = n_steps everywhere EXCEPT the 39x39 cone region (which
// the sim kernel writes) -> disjoint from sim, safe to run concurrently.
// ---------------------------------------------------------------------------
__global__ void __launch_bounds__(256)
fill_kernel(float4* __restrict__ out4,
            const int* __restrict__ ip,
            const int* __restrict__ nsp) {
    int or0 = ip[0] - RC;
    int oc0 = ip[1] - RC;
    float v = (float)(*nsp);
    float4 f = make_float4(v, v, v, v);
    float* out = (float*)out4;
    int base = blockIdx.x * 256 + threadIdx.x;
    #pragma unroll
    for (int g = 0; g < 2; g++) {
        int fi = base + g * (FILLB * 256);
        int row = fi >> 8;                 // 256 float4 per row
        int col = (fi & 255) << 2;
        bool rowin = (row >= or0) && (row < or0 + REG);
        bool colov = (col + 3 >= oc0) && (col <= oc0 + REG - 1);
        if (!(rowin && colov)) {
            out4[fi] = f;
        } else {
            #pragma unroll
            for (int e = 0; e < 4; e++) {
                int cc = col + e;
                if (cc < oc0 || cc >= oc0 + REG)
                    out[row * WW + cc] = v;
            }
        }
    }
}

// ---------------------------------------------------------------------------
extern "C" void kernel_launch(void* const* d_in, const int* in_sizes, int n_in,
                              void* d_out, int out_size) {
    const float* height   = (const float*)d_in[0];
    const float* age      = (const float*)d_in[1];
    const float* moisture = (const float*)d_in[2];
    const float* la       = (const float*)d_in[3];
    const float* lb       = (const float*)d_in[4];
    const float* lg       = (const float*)d_in[5];
    const float* ld       = (const float*)d_in[6];
    const float* ws       = (const float*)d_in[7];
    const float* wd       = (const float*)d_in[8];
    const float* ignv     = (const float*)d_in[9];
    const int*   ip       = (const int*)d_in[10];
    const int*   ns       = (const int*)d_in[11];
    const int*   nss      = (const int*)d_in[12];
    float* out = (float*)d_out;

    // K1: coefficients only (small)
    coef_kernel<<<COEFB, 256>>>(height, age, moisture,
                                la, lb, lg, ld, ws, wd, ip);

    cudaLaunchAttribute attr[1];
    attr[0].id = cudaLaunchAttributeProgrammaticStreamSerialization;
    attr[0].val.programmaticStreamSerializationAllowed = 1;

    // K2: sim — starts while K1 drains; waits only on coefs; triggers K3 at entry
    cudaLaunchConfig_t cfg = {};
    cfg.gridDim  = dim3(1, 1, 1);
    cfg.blockDim = dim3(NSIM, 1, 1);
    cfg.attrs = attr;
    cfg.numAttrs = 1;
    cudaLaunchKernelEx(&cfg, sim_kernel, ignv, ip, ns, nss, out);

    // K3: cone-excluded fill — runs concurrently with the sim loop
    cudaLaunchConfig_t cfg2 = {};
    cfg2.gridDim  = dim3(FILLB, 1, 1);
    cfg2.blockDim = dim3(256, 1, 1);
    cfg2.attrs = attr;
    cfg2.numAttrs = 1;
    cudaLaunchKernelEx(&cfg2, fill_kernel, (float4*)out, ip, ns);
}